// round 2
// baseline (speedup 1.0000x reference)
#include <cuda_runtime.h>
#include <math.h>
#include <stdint.h>

#define NNODES 32768
#define NEDGES 524288
#define NPG    2048
#define NGRAPH 16
#define K1     1024
#define NP1    16384   // NGRAPH*K1
#define K2     512
#define NP2    8192    // NGRAPH*K2

// ---------------- static scratch (no allocations allowed) ----------------
__device__ float g_bufA[NNODES * 256];   // GEMM outputs (GAT transformed feats)
__device__ float g_bufB[NNODES * 256];   // GAT aggregated outputs
__device__ float g_as[NNODES * 4];
__device__ float g_ad[NNODES * 4];
__device__ float g_feat1[NNODES * 128];  // gcn1 gemm out
__device__ float g_feat2[NNODES * 128];  // gcn1 aggregated out
__device__ float g_x1p[NP1 * 128];       // pooled-1 features
__device__ float g_h3[NP1 * 128];        // gcn2 gemm out
__device__ float g_x2[NP1 * 128];        // gcn2 aggregated out
__device__ float g_x2p[NP2 * 128];       // pooled-2 features
__device__ float g_score[NNODES];
__device__ float g_dinv[NNODES];
__device__ int   g_cnt[NNODES];
__device__ int   g_fill[NNODES];
__device__ int   g_rowoff[NNODES + 1];
__device__ int   g_csrsrc[NEDGES];
__device__ int   g_perm1[NP1];
__device__ int   g_newid1[NNODES];
__device__ int   g_perm2[NP2];
__device__ int   g_newid2[NP1];
__device__ float g_pool[NGRAPH * 128];

__device__ __forceinline__ float lrelu(float x) { return x > 0.f ? x : 0.2f * x; }

// ---------------- CSR build ----------------
__global__ void zero2_kernel(int* p0, int* p1, int n) {
    int i = blockIdx.x * blockDim.x + threadIdx.x;
    if (i < n) { p0[i] = 0; p1[i] = 0; }
}

__global__ void count_dst_kernel(const int* __restrict__ dst, int* __restrict__ cnt) {
    int e = blockIdx.x * blockDim.x + threadIdx.x;
    if (e < NEDGES) atomicAdd(&cnt[dst[e]], 1);
}

__global__ void scan_kernel(const int* __restrict__ cnt, int* __restrict__ rowoff) {
    __shared__ int sh[1024];
    int tid = threadIdx.x;
    int run = 0;
    for (int base = 0; base < NNODES; base += 1024) {
        sh[tid] = cnt[base + tid];
        __syncthreads();
        for (int off = 1; off < 1024; off <<= 1) {
            int t = (tid >= off) ? sh[tid - off] : 0;
            __syncthreads();
            sh[tid] += t;
            __syncthreads();
        }
        rowoff[base + tid + 1] = run + sh[tid];
        int tot = sh[1023];
        __syncthreads();
        run += tot;
    }
    if (tid == 0) rowoff[0] = 0;
}

__global__ void fill_csr_kernel(const int* __restrict__ src, const int* __restrict__ dst,
                                const int* __restrict__ rowoff, int* __restrict__ fill,
                                int* __restrict__ csr) {
    int e = blockIdx.x * blockDim.x + threadIdx.x;
    if (e >= NEDGES) return;
    int d = dst[e];
    int pos = rowoff[d] + atomicAdd(&fill[d], 1);
    csr[pos] = src[e];
}

// ---------------- GEMM: C[M,Nn] = A[M,K] * W[Nn,K]^T ----------------
// BM=BN=128, BK=16, 256 threads, 8x8 per thread. Requires M%128==0, Nn%128==0, K%16==0.
__global__ void __launch_bounds__(256) gemm_nt(const float* __restrict__ A,
                                               const float* __restrict__ W,
                                               float* __restrict__ C,
                                               int M, int Nn, int K) {
    __shared__ float As[16][132];
    __shared__ float Ws[16][132];
    int bm = blockIdx.y * 128, bn = blockIdx.x * 128;
    int tid = threadIdx.x;
    int tx = tid & 15, ty = tid >> 4;
    float acc[8][8];
#pragma unroll
    for (int i = 0; i < 8; ++i)
#pragma unroll
        for (int j = 0; j < 8; ++j) acc[i][j] = 0.f;

    for (int k0 = 0; k0 < K; k0 += 16) {
#pragma unroll
        for (int l = 0; l < 8; ++l) {
            int idx = tid + l * 256;
            int kk = idx & 15, r = idx >> 4;
            As[kk][r] = A[(size_t)(bm + r) * K + k0 + kk];
            Ws[kk][r] = W[(size_t)(bn + r) * K + k0 + kk];
        }
        __syncthreads();
#pragma unroll
        for (int kk = 0; kk < 16; ++kk) {
            float a[8], b[8];
            float4 a0 = *reinterpret_cast<const float4*>(&As[kk][ty * 8]);
            float4 a1 = *reinterpret_cast<const float4*>(&As[kk][ty * 8 + 4]);
            float4 b0 = *reinterpret_cast<const float4*>(&Ws[kk][tx * 8]);
            float4 b1 = *reinterpret_cast<const float4*>(&Ws[kk][tx * 8 + 4]);
            a[0] = a0.x; a[1] = a0.y; a[2] = a0.z; a[3] = a0.w;
            a[4] = a1.x; a[5] = a1.y; a[6] = a1.z; a[7] = a1.w;
            b[0] = b0.x; b[1] = b0.y; b[2] = b0.z; b[3] = b0.w;
            b[4] = b1.x; b[5] = b1.y; b[6] = b1.z; b[7] = b1.w;
#pragma unroll
            for (int i = 0; i < 8; ++i)
#pragma unroll
                for (int j = 0; j < 8; ++j) acc[i][j] += a[i] * b[j];
        }
        __syncthreads();
    }
#pragma unroll
    for (int i = 0; i < 8; ++i) {
        int row = bm + ty * 8 + i;
        float4* cp = reinterpret_cast<float4*>(&C[(size_t)row * Nn + bn + tx * 8]);
        cp[0] = make_float4(acc[i][0], acc[i][1], acc[i][2], acc[i][3]);
        cp[1] = make_float4(acc[i][4], acc[i][5], acc[i][6], acc[i][7]);
    }
}

// ---------------- GAT ----------------
__global__ void attn_sums_kernel(const float* __restrict__ H, const float* __restrict__ asrc,
                                 const float* __restrict__ adst, float* __restrict__ as_,
                                 float* __restrict__ ad_) {
    int idx = blockIdx.x * blockDim.x + threadIdx.x;
    if (idx >= NNODES * 4) return;
    int i = idx >> 2, h = idx & 3;
    const float* hp = H + (size_t)i * 256 + h * 64;
    const float* ws = asrc + h * 64;
    const float* wd = adst + h * 64;
    float s1 = 0.f, s2 = 0.f;
#pragma unroll
    for (int c = 0; c < 64; ++c) { float v = hp[c]; s1 += v * ws[c]; s2 += v * wd[c]; }
    as_[idx] = s1;
    ad_[idx] = s2;
}

// One block per dst node. Phase 1: 4 warps compute per-head softmax max & denom
// (incl. the appended self loop). Phase 2: 256 threads (one per output channel)
// aggregate alpha-weighted source features. No atomics.
__global__ void __launch_bounds__(256) gat_aggr_kernel(const float* __restrict__ H,
        const float* __restrict__ as_, const float* __restrict__ ad_,
        const float* __restrict__ bias, const int* __restrict__ rowoff,
        const int* __restrict__ csrsrc, float* __restrict__ out, int relu) {
    int d = blockIdx.x;
    int tid = threadIdx.x;
    __shared__ float smax[4], sden[4];
    int r0 = rowoff[d], r1 = rowoff[d + 1];
    if (tid < 128) {
        int h = tid >> 5, lane = tid & 31;
        float adh = ad_[d * 4 + h];
        float es = lrelu(as_[d * 4 + h] + adh);
        float lmax = (lane == 0) ? es : -1e30f;
        for (int j = r0 + lane; j < r1; j += 32)
            lmax = fmaxf(lmax, lrelu(as_[csrsrc[j] * 4 + h] + adh));
#pragma unroll
        for (int o = 16; o; o >>= 1) lmax = fmaxf(lmax, __shfl_xor_sync(0xffffffffu, lmax, o));
        float lsum = (lane == 0) ? __expf(es - lmax) : 0.f;
        for (int j = r0 + lane; j < r1; j += 32)
            lsum += __expf(lrelu(as_[csrsrc[j] * 4 + h] + adh) - lmax);
#pragma unroll
        for (int o = 16; o; o >>= 1) lsum += __shfl_xor_sync(0xffffffffu, lsum, o);
        if (lane == 0) { smax[h] = lmax; sden[h] = lsum + 1e-16f; }
    }
    __syncthreads();
    int c = tid, h = tid >> 6;
    float m = smax[h];
    float inv = 1.f / sden[h];
    float adh = ad_[d * 4 + h];
    float acc = __expf(lrelu(as_[d * 4 + h] + adh) - m) * inv * H[(size_t)d * 256 + c];
    for (int j = r0; j < r1; ++j) {
        int s = csrsrc[j];
        acc += __expf(lrelu(as_[s * 4 + h] + adh) - m) * inv * H[(size_t)s * 256 + c];
    }
    float v = acc + bias[c];
    out[(size_t)d * 256 + c] = relu ? fmaxf(v, 0.f) : v;
}

// ---------------- GCN ----------------
__global__ void dinv1_kernel(const int* __restrict__ rowoff, float* __restrict__ dinv) {
    int d = blockIdx.x * blockDim.x + threadIdx.x;
    if (d >= NNODES) return;
    dinv[d] = rsqrtf((float)(rowoff[d + 1] - rowoff[d] + 1));
}

__global__ void gcn1_aggr_kernel(const float* __restrict__ G, const float* __restrict__ dinv,
                                 const float* __restrict__ bias, const int* __restrict__ rowoff,
                                 const int* __restrict__ csrsrc, float* __restrict__ out) {
    int d = blockIdx.x;
    int c = threadIdx.x;
    float dd = dinv[d];
    float acc = dd * dd * G[(size_t)d * 128 + c];
    int r1 = rowoff[d + 1];
    for (int j = rowoff[d]; j < r1; ++j) {
        int s = csrsrc[j];
        acc += dinv[s] * dd * G[(size_t)s * 128 + c];
    }
    out[(size_t)d * 128 + c] = fmaxf(acc + bias[c], 0.f);
}

__global__ void gcn2_deg_kernel(const int* __restrict__ perm1, const int* __restrict__ newid1,
                                const int* __restrict__ rowoff, const int* __restrict__ csrsrc,
                                float* __restrict__ dinv) {
    int d1 = blockIdx.x * blockDim.x + threadIdx.x;
    if (d1 >= NP1) return;
    int D = perm1[d1];
    int cnt = 1;  // +1 self loop
    int r1 = rowoff[D + 1];
    for (int j = rowoff[D]; j < r1; ++j)
        if (newid1[csrsrc[j]] >= 0) cnt++;
    dinv[d1] = rsqrtf((float)cnt);
}

__global__ void gcn2_aggr_kernel(const float* __restrict__ G, const float* __restrict__ dinv,
                                 const float* __restrict__ bias, const int* __restrict__ perm1,
                                 const int* __restrict__ newid1, const int* __restrict__ rowoff,
                                 const int* __restrict__ csrsrc, float* __restrict__ out) {
    int d1 = blockIdx.x;
    int c = threadIdx.x;
    int D = perm1[d1];
    float dd = dinv[d1];
    float acc = dd * dd * G[(size_t)d1 * 128 + c];
    int r1 = rowoff[D + 1];
    for (int j = rowoff[D]; j < r1; ++j) {
        int s1 = newid1[csrsrc[j]];
        if (s1 >= 0) acc += dinv[s1] * dd * G[(size_t)s1 * 128 + c];
    }
    out[(size_t)d1 * 128 + c] = fmaxf(acc + bias[c], 0.f);
}

// ---------------- SAG scores ----------------
__global__ void score1_kernel(const float* __restrict__ X, const float* __restrict__ wrel,
                              const float* __restrict__ brel, const float* __restrict__ wroot,
                              const int* __restrict__ rowoff, const int* __restrict__ csrsrc,
                              float* __restrict__ score) {
    int d = blockIdx.x;
    int c = threadIdx.x;  // 128
    float aggc = 0.f;
    int r1 = rowoff[d + 1];
    for (int j = rowoff[d]; j < r1; ++j) aggc += X[(size_t)csrsrc[j] * 128 + c];
    float part = aggc * wrel[c] + X[(size_t)d * 128 + c] * wroot[c];
    __shared__ float sw[4];
#pragma unroll
    for (int o = 16; o; o >>= 1) part += __shfl_xor_sync(0xffffffffu, part, o);
    if ((c & 31) == 0) sw[c >> 5] = part;
    __syncthreads();
    if (c == 0) score[d] = sw[0] + sw[1] + sw[2] + sw[3] + brel[0];
}

__global__ void score2_kernel(const float* __restrict__ X, const float* __restrict__ wrel,
                              const float* __restrict__ brel, const float* __restrict__ wroot,
                              const int* __restrict__ rowoff, const int* __restrict__ csrsrc,
                              const int* __restrict__ perm1, const int* __restrict__ newid1,
                              float* __restrict__ score) {
    int d1 = blockIdx.x;
    int c = threadIdx.x;
    int D = perm1[d1];
    float aggc = 0.f;
    int r1 = rowoff[D + 1];
    for (int j = rowoff[D]; j < r1; ++j) {
        int s1 = newid1[csrsrc[j]];
        if (s1 >= 0) aggc += X[(size_t)s1 * 128 + c];
    }
    float part = aggc * wrel[c] + X[(size_t)d1 * 128 + c] * wroot[c];
    __shared__ float sw[4];
#pragma unroll
    for (int o = 16; o; o >>= 1) part += __shfl_xor_sync(0xffffffffu, part, o);
    if ((c & 31) == 0) sw[c >> 5] = part;
    __syncthreads();
    if (c == 0) score[d1] = sw[0] + sw[1] + sw[2] + sw[3] + brel[0];
}

// ---------------- per-graph top-k via bitonic sort ----------------
// key = (~flip(score) << 32) | idx  -> ascending sort = value desc, index asc tiebreak.
template <int NS>
__global__ void __launch_bounds__(1024) topk_kernel(const float* __restrict__ score, int k,
                                                    int* __restrict__ perm, int* __restrict__ newid) {
    __shared__ unsigned long long keys[NS];
    int g = blockIdx.x;
    int tid = threadIdx.x;
    for (int i = tid; i < NS; i += 1024) {
        float v = score[g * NS + i];
        unsigned u = __float_as_uint(v);
        u = (u & 0x80000000u) ? ~u : (u | 0x80000000u);  // monotone increasing
        u = ~u;                                          // monotone decreasing
        keys[i] = ((unsigned long long)u << 32) | (unsigned)i;
        newid[g * NS + i] = -1;
    }
    __syncthreads();
    for (int ksz = 2; ksz <= NS; ksz <<= 1) {
        for (int j = ksz >> 1; j > 0; j >>= 1) {
            for (int i = tid; i < NS; i += 1024) {
                int ixj = i ^ j;
                if (ixj > i) {
                    bool up = ((i & ksz) == 0);
                    unsigned long long a = keys[i], b = keys[ixj];
                    if ((a > b) == up) { keys[i] = b; keys[ixj] = a; }
                }
            }
            __syncthreads();
        }
    }
    for (int r = tid; r < k; r += 1024) {
        int i = (int)(keys[r] & 0xFFFFFFFFu);
        int orig = g * NS + i;
        perm[g * k + r] = orig;
        newid[orig] = g * k + r;
    }
}

__global__ void gather_tanh_kernel(const float* __restrict__ X, const float* __restrict__ score,
                                   const int* __restrict__ perm, float* __restrict__ Xp, int np) {
    int idx = blockIdx.x * blockDim.x + threadIdx.x;
    if (idx >= np * 128) return;
    int p = idx >> 7, c = idx & 127;
    int o = perm[p];
    Xp[idx] = X[(size_t)o * 128 + c] * tanhf(score[o]);
}

// ---------------- pooling + MLP ----------------
__global__ void meanpool_kernel(const float* __restrict__ Xp2, float* __restrict__ g) {
    int gr = blockIdx.x;
    int c = threadIdx.x;  // 128
    float s = 0.f;
    for (int j = 0; j < K2; ++j) s += Xp2[(size_t)(gr * K2 + j) * 128 + c];
    g[gr * 128 + c] = s * (1.f / (float)K2);
}

__global__ void mlp_kernel(const float* __restrict__ g,
                           const float* __restrict__ fc1_w, const float* __restrict__ fc1_b,
                           const float* __restrict__ fc2_w, const float* __restrict__ fc2_b,
                           const float* __restrict__ out_w, const float* __restrict__ out_b,
                           float* __restrict__ out) {
    int gr = blockIdx.x;
    int t = threadIdx.x;  // 256
    __shared__ float xin[128], a1[256], a2[128];
    if (t < 128) xin[t] = g[gr * 128 + t];
    __syncthreads();
    {
        float s = fc1_b[t];
#pragma unroll 4
        for (int c = 0; c < 128; ++c) s += fc1_w[t * 128 + c] * xin[c];
        a1[t] = fmaxf(s, 0.f);
    }
    __syncthreads();
    if (t < 128) {
        float s = fc2_b[t];
#pragma unroll 4
        for (int c = 0; c < 256; ++c) s += fc2_w[t * 256 + c] * a1[c];
        a2[t] = fmaxf(s, 0.f);
    }
    __syncthreads();
    if (t < 10) {
        float s = out_b[t];
#pragma unroll 4
        for (int c = 0; c < 128; ++c) s += out_w[t * 128 + c] * a2[c];
        out[gr * 10 + t] = s;
    }
}

// ---------------- launch ----------------
extern "C" void kernel_launch(void* const* d_in, const int* in_sizes, int n_in,
                              void* d_out, int out_size) {
    const float* x         = (const float*)d_in[0];
    const int*   src       = (const int*)d_in[1];
    const int*   dst       = src + NEDGES;
    const float* gat1_w    = (const float*)d_in[3];
    const float* gat1_asrc = (const float*)d_in[4];
    const float* gat1_adst = (const float*)d_in[5];
    const float* gat1_b    = (const float*)d_in[6];
    const float* gat2_w    = (const float*)d_in[7];
    const float* gat2_asrc = (const float*)d_in[8];
    const float* gat2_adst = (const float*)d_in[9];
    const float* gat2_b    = (const float*)d_in[10];
    const float* gcn1_w    = (const float*)d_in[11];
    const float* gcn1_b    = (const float*)d_in[12];
    const float* sag1_wrel = (const float*)d_in[13];
    const float* sag1_brel = (const float*)d_in[14];
    const float* sag1_wroot= (const float*)d_in[15];
    const float* gcn2_w    = (const float*)d_in[16];
    const float* gcn2_b    = (const float*)d_in[17];
    const float* sag2_wrel = (const float*)d_in[18];
    const float* sag2_brel = (const float*)d_in[19];
    const float* sag2_wroot= (const float*)d_in[20];
    const float* fc1_w     = (const float*)d_in[21];
    const float* fc1_b     = (const float*)d_in[22];
    const float* fc2_w     = (const float*)d_in[23];
    const float* fc2_b     = (const float*)d_in[24];
    const float* out_w     = (const float*)d_in[25];
    const float* out_b     = (const float*)d_in[26];
    float* outp = (float*)d_out;

    float *pA, *pB, *pAS, *pAD, *pF1, *pF2, *pX1P, *pH3, *pX2, *pX2P, *pScore, *pDinv, *pPool;
    int *pCnt, *pFill, *pRow, *pCsr, *pPerm1, *pNew1, *pPerm2, *pNew2;
    cudaGetSymbolAddress((void**)&pA, g_bufA);
    cudaGetSymbolAddress((void**)&pB, g_bufB);
    cudaGetSymbolAddress((void**)&pAS, g_as);
    cudaGetSymbolAddress((void**)&pAD, g_ad);
    cudaGetSymbolAddress((void**)&pF1, g_feat1);
    cudaGetSymbolAddress((void**)&pF2, g_feat2);
    cudaGetSymbolAddress((void**)&pX1P, g_x1p);
    cudaGetSymbolAddress((void**)&pH3, g_h3);
    cudaGetSymbolAddress((void**)&pX2, g_x2);
    cudaGetSymbolAddress((void**)&pX2P, g_x2p);
    cudaGetSymbolAddress((void**)&pScore, g_score);
    cudaGetSymbolAddress((void**)&pDinv, g_dinv);
    cudaGetSymbolAddress((void**)&pPool, g_pool);
    cudaGetSymbolAddress((void**)&pCnt, g_cnt);
    cudaGetSymbolAddress((void**)&pFill, g_fill);
    cudaGetSymbolAddress((void**)&pRow, g_rowoff);
    cudaGetSymbolAddress((void**)&pCsr, g_csrsrc);
    cudaGetSymbolAddress((void**)&pPerm1, g_perm1);
    cudaGetSymbolAddress((void**)&pNew1, g_newid1);
    cudaGetSymbolAddress((void**)&pPerm2, g_perm2);
    cudaGetSymbolAddress((void**)&pNew2, g_newid2);

    // ---- CSR by dst (rebuilt every launch; inputs are fixed) ----
    zero2_kernel<<<(NNODES + 255) / 256, 256>>>(pCnt, pFill, NNODES);
    count_dst_kernel<<<(NEDGES + 255) / 256, 256>>>(dst, pCnt);
    scan_kernel<<<1, 1024>>>(pCnt, pRow);
    fill_csr_kernel<<<(NEDGES + 255) / 256, 256>>>(src, dst, pRow, pFill, pCsr);

    // ---- GAT1 (64 -> 4x64, relu) ----
    gemm_nt<<<dim3(256 / 128, NNODES / 128), 256>>>(x, gat1_w, pA, NNODES, 256, 64);
    attn_sums_kernel<<<(NNODES * 4 + 255) / 256, 256>>>(pA, gat1_asrc, gat1_adst, pAS, pAD);
    gat_aggr_kernel<<<NNODES, 256>>>(pA, pAS, pAD, gat1_b, pRow, pCsr, pB, 1);

    // ---- GAT2 (256 -> 4x64) ----
    gemm_nt<<<dim3(2, NNODES / 128), 256>>>(pB, gat2_w, pA, NNODES, 256, 256);
    attn_sums_kernel<<<(NNODES * 4 + 255) / 256, 256>>>(pA, gat2_asrc, gat2_adst, pAS, pAD);
    gat_aggr_kernel<<<NNODES, 256>>>(pA, pAS, pAD, gat2_b, pRow, pCsr, pB, 0);

    // ---- GCN1 (256 -> 128, relu) ----
    gemm_nt<<<dim3(1, NNODES / 128), 256>>>(pB, gcn1_w, pF1, NNODES, 128, 256);
    dinv1_kernel<<<(NNODES + 255) / 256, 256>>>(pRow, pDinv);
    gcn1_aggr_kernel<<<NNODES, 128>>>(pF1, pDinv, gcn1_b, pRow, pCsr, pF2);

    // ---- SAGPool1 (ratio .5) ----
    score1_kernel<<<NNODES, 128>>>(pF2, sag1_wrel, sag1_brel, sag1_wroot, pRow, pCsr, pScore);
    topk_kernel<NPG><<<NGRAPH, 1024>>>(pScore, K1, pPerm1, pNew1);
    gather_tanh_kernel<<<(NP1 * 128 + 255) / 256, 256>>>(pF2, pScore, pPerm1, pX1P, NP1);

    // ---- GCN2 (128 -> 128, relu) on pooled graph via original CSR + remap ----
    gemm_nt<<<dim3(1, NP1 / 128), 256>>>(pX1P, gcn2_w, pH3, NP1, 128, 128);
    gcn2_deg_kernel<<<(NP1 + 255) / 256, 256>>>(pPerm1, pNew1, pRow, pCsr, pDinv);
    gcn2_aggr_kernel<<<NP1, 128>>>(pH3, pDinv, gcn2_b, pPerm1, pNew1, pRow, pCsr, pX2);

    // ---- SAGPool2 ----
    score2_kernel<<<NP1, 128>>>(pX2, sag2_wrel, sag2_brel, sag2_wroot, pRow, pCsr, pPerm1, pNew1, pScore);
    topk_kernel<K1><<<NGRAPH, 1024>>>(pScore, K2, pPerm2, pNew2);
    gather_tanh_kernel<<<(NP2 * 128 + 255) / 256, 256>>>(pX2, pScore, pPerm2, pX2P, NP2);

    // ---- global mean pool + classifier ----
    meanpool_kernel<<<NGRAPH, 128>>>(pX2P, pPool);
    mlp_kernel<<<NGRAPH, 256>>>(pPool, fc1_w, fc1_b, fc2_w, fc2_b, out_w, out_b, outp);
}

// round 3
// speedup vs baseline: 1.1025x; 1.1025x over previous
#include <cuda_runtime.h>
#include <math.h>
#include <stdint.h>

#define NNODES 32768
#define NEDGES 524288
#define NPG    2048
#define NGRAPH 16
#define K1     1024
#define NP1    16384   // NGRAPH*K1
#define K2     512
#define NP2    8192    // NGRAPH*K2

// ---------------- static scratch (no allocations allowed) ----------------
__device__ float g_bufA[NNODES * 256];   // GEMM outputs (GAT transformed feats)
__device__ float g_bufB[NNODES * 256];   // GAT aggregated outputs
__device__ float g_as[NNODES * 4];
__device__ float g_ad[NNODES * 4];
__device__ float g_feat1[NNODES * 128];  // gcn1 gemm out
__device__ float g_feat2[NNODES * 128];  // gcn1 aggregated out
__device__ float g_x1p[NP1 * 128];       // pooled-1 features
__device__ float g_h3[NP1 * 128];        // gcn2 gemm out
__device__ float g_x2[NP1 * 128];        // gcn2 aggregated out
__device__ float g_x2p[NP2 * 128];       // pooled-2 features
__device__ float g_score[NNODES];
__device__ float g_dinv[NNODES];
__device__ int   g_cnt[NNODES];
__device__ int   g_fill[NNODES];
__device__ int   g_rowoff[NNODES + 1];
__device__ int   g_csrsrc[NEDGES];
__device__ int   g_perm1[NP1];
__device__ int   g_newid1[NNODES];
__device__ int   g_perm2[NP2];
__device__ int   g_newid2[NP1];
__device__ float g_pool[NGRAPH * 128];

__device__ __forceinline__ float lrelu(float x) { return x > 0.f ? x : 0.2f * x; }

// ---------------- CSR build ----------------
__global__ void zero2_kernel(int* p0, int* p1, int n) {
    int i = blockIdx.x * blockDim.x + threadIdx.x;
    if (i < n) { p0[i] = 0; p1[i] = 0; }
}

__global__ void count_dst_kernel(const int* __restrict__ dst, int* __restrict__ cnt) {
    int e = blockIdx.x * blockDim.x + threadIdx.x;
    if (e < NEDGES) atomicAdd(&cnt[dst[e]], 1);
}

__global__ void scan_kernel(const int* __restrict__ cnt, int* __restrict__ rowoff) {
    __shared__ int sh[1024];
    int tid = threadIdx.x;
    int run = 0;
    for (int base = 0; base < NNODES; base += 1024) {
        sh[tid] = cnt[base + tid];
        __syncthreads();
        for (int off = 1; off < 1024; off <<= 1) {
            int t = (tid >= off) ? sh[tid - off] : 0;
            __syncthreads();
            sh[tid] += t;
            __syncthreads();
        }
        rowoff[base + tid + 1] = run + sh[tid];
        int tot = sh[1023];
        __syncthreads();
        run += tot;
    }
    if (tid == 0) rowoff[0] = 0;
}

__global__ void fill_csr_kernel(const int* __restrict__ src, const int* __restrict__ dst,
                                const int* __restrict__ rowoff, int* __restrict__ fill,
                                int* __restrict__ csr) {
    int e = blockIdx.x * blockDim.x + threadIdx.x;
    if (e >= NEDGES) return;
    int d = dst[e];
    int pos = rowoff[d] + atomicAdd(&fill[d], 1);
    csr[pos] = src[e];
}

// ---------------- GEMM: C[M,Nn] = A[M,K] * W[Nn,K]^T ----------------
__global__ void __launch_bounds__(256) gemm_nt(const float* __restrict__ A,
                                               const float* __restrict__ W,
                                               float* __restrict__ C,
                                               int M, int Nn, int K) {
    __shared__ float As[16][132];
    __shared__ float Ws[16][132];
    int bm = blockIdx.y * 128, bn = blockIdx.x * 128;
    int tid = threadIdx.x;
    int tx = tid & 15, ty = tid >> 4;
    float acc[8][8];
#pragma unroll
    for (int i = 0; i < 8; ++i)
#pragma unroll
        for (int j = 0; j < 8; ++j) acc[i][j] = 0.f;

    for (int k0 = 0; k0 < K; k0 += 16) {
#pragma unroll
        for (int l = 0; l < 8; ++l) {
            int idx = tid + l * 256;
            int kk = idx & 15, r = idx >> 4;
            As[kk][r] = A[(size_t)(bm + r) * K + k0 + kk];
            Ws[kk][r] = W[(size_t)(bn + r) * K + k0 + kk];
        }
        __syncthreads();
#pragma unroll
        for (int kk = 0; kk < 16; ++kk) {
            float a[8], b[8];
            float4 a0 = *reinterpret_cast<const float4*>(&As[kk][ty * 8]);
            float4 a1 = *reinterpret_cast<const float4*>(&As[kk][ty * 8 + 4]);
            float4 b0 = *reinterpret_cast<const float4*>(&Ws[kk][tx * 8]);
            float4 b1 = *reinterpret_cast<const float4*>(&Ws[kk][tx * 8 + 4]);
            a[0] = a0.x; a[1] = a0.y; a[2] = a0.z; a[3] = a0.w;
            a[4] = a1.x; a[5] = a1.y; a[6] = a1.z; a[7] = a1.w;
            b[0] = b0.x; b[1] = b0.y; b[2] = b0.z; b[3] = b0.w;
            b[4] = b1.x; b[5] = b1.y; b[6] = b1.z; b[7] = b1.w;
#pragma unroll
            for (int i = 0; i < 8; ++i)
#pragma unroll
                for (int j = 0; j < 8; ++j) acc[i][j] += a[i] * b[j];
        }
        __syncthreads();
    }
#pragma unroll
    for (int i = 0; i < 8; ++i) {
        int row = bm + ty * 8 + i;
        float4* cp = reinterpret_cast<float4*>(&C[(size_t)row * Nn + bn + tx * 8]);
        cp[0] = make_float4(acc[i][0], acc[i][1], acc[i][2], acc[i][3]);
        cp[1] = make_float4(acc[i][4], acc[i][5], acc[i][6], acc[i][7]);
    }
}

// ---------------- GAT ----------------
__global__ void attn_sums_kernel(const float* __restrict__ H, const float* __restrict__ asrc,
                                 const float* __restrict__ adst, float* __restrict__ as_,
                                 float* __restrict__ ad_) {
    int idx = blockIdx.x * blockDim.x + threadIdx.x;
    if (idx >= NNODES * 4) return;
    int i = idx >> 2, h = idx & 3;
    const float* hp = H + (size_t)i * 256 + h * 64;
    const float* ws = asrc + h * 64;
    const float* wd = adst + h * 64;
    float s1 = 0.f, s2 = 0.f;
#pragma unroll
    for (int c = 0; c < 64; ++c) { float v = hp[c]; s1 += v * ws[c]; s2 += v * wd[c]; }
    as_[idx] = s1;
    ad_[idx] = s2;
}

// One block per dst node.
// Phase 1: 4 warps compute per-head softmax max & denom (incl. self loop) and the
// self-loop alpha. Phase 2: edges processed in chunks of 32; 128 threads precompute
// alpha/den per (edge,head) into smem once, then 256 threads (one per output
// channel) accumulate coalesced rows. expf count drops from E*256 to E*4.
#define GAT_CH 32
__global__ void __launch_bounds__(256) gat_aggr_kernel(const float* __restrict__ H,
        const float* __restrict__ as_, const float* __restrict__ ad_,
        const float* __restrict__ bias, const int* __restrict__ rowoff,
        const int* __restrict__ csrsrc, float* __restrict__ out, int relu) {
    int d = blockIdx.x;
    int tid = threadIdx.x;
    __shared__ float smax[4], sinv[4], sself[4];
    __shared__ float salpha[4][GAT_CH];
    __shared__ int   ssrc[GAT_CH];
    int r0 = rowoff[d], r1 = rowoff[d + 1];
    if (tid < 128) {
        int h = tid >> 5, lane = tid & 31;
        float adh = ad_[d * 4 + h];
        float es = lrelu(as_[d * 4 + h] + adh);
        float lmax = (lane == 0) ? es : -1e30f;
        for (int j = r0 + lane; j < r1; j += 32)
            lmax = fmaxf(lmax, lrelu(as_[csrsrc[j] * 4 + h] + adh));
#pragma unroll
        for (int o = 16; o; o >>= 1) lmax = fmaxf(lmax, __shfl_xor_sync(0xffffffffu, lmax, o));
        float lsum = (lane == 0) ? __expf(es - lmax) : 0.f;
        for (int j = r0 + lane; j < r1; j += 32)
            lsum += __expf(lrelu(as_[csrsrc[j] * 4 + h] + adh) - lmax);
#pragma unroll
        for (int o = 16; o; o >>= 1) lsum += __shfl_xor_sync(0xffffffffu, lsum, o);
        if (lane == 0) {
            float inv = 1.f / (lsum + 1e-16f);
            smax[h] = lmax;
            sinv[h] = inv;
            sself[h] = __expf(es - lmax) * inv;
        }
    }
    __syncthreads();
    int c = tid, h = tid >> 6;
    float acc = sself[h] * H[(size_t)d * 256 + c];
    for (int base = r0; base < r1; base += GAT_CH) {
        int cnt = min(GAT_CH, r1 - base);
        if (tid < 128) {
            int hh = tid >> 5, e = tid & 31;
            if (e < cnt) {
                int s = csrsrc[base + e];
                float a = __expf(lrelu(as_[s * 4 + hh] + ad_[d * 4 + hh]) - smax[hh]) * sinv[hh];
                salpha[hh][e] = a;
                if (hh == 0) ssrc[e] = s;
            }
        }
        __syncthreads();
        for (int i = 0; i < cnt; ++i)
            acc += salpha[h][i] * H[(size_t)ssrc[i] * 256 + c];
        __syncthreads();
    }
    float v = acc + bias[c];
    out[(size_t)d * 256 + c] = relu ? fmaxf(v, 0.f) : v;
}

// ---------------- GCN ----------------
__global__ void dinv1_kernel(const int* __restrict__ rowoff, float* __restrict__ dinv) {
    int d = blockIdx.x * blockDim.x + threadIdx.x;
    if (d >= NNODES) return;
    dinv[d] = rsqrtf((float)(rowoff[d + 1] - rowoff[d] + 1));
}

__global__ void gcn1_aggr_kernel(const float* __restrict__ G, const float* __restrict__ dinv,
                                 const float* __restrict__ bias, const int* __restrict__ rowoff,
                                 const int* __restrict__ csrsrc, float* __restrict__ out) {
    int d = blockIdx.x;
    int c = threadIdx.x;
    float dd = dinv[d];
    float acc = dd * dd * G[(size_t)d * 128 + c];
    int r1 = rowoff[d + 1];
    for (int j = rowoff[d]; j < r1; ++j) {
        int s = csrsrc[j];
        acc += dinv[s] * dd * G[(size_t)s * 128 + c];
    }
    out[(size_t)d * 128 + c] = fmaxf(acc + bias[c], 0.f);
}

__global__ void gcn2_deg_kernel(const int* __restrict__ perm1, const int* __restrict__ newid1,
                                const int* __restrict__ rowoff, const int* __restrict__ csrsrc,
                                float* __restrict__ dinv) {
    int d1 = blockIdx.x * blockDim.x + threadIdx.x;
    if (d1 >= NP1) return;
    int D = perm1[d1];
    int cnt = 1;  // +1 self loop
    int r1 = rowoff[D + 1];
    for (int j = rowoff[D]; j < r1; ++j)
        if (newid1[csrsrc[j]] >= 0) cnt++;
    dinv[d1] = rsqrtf((float)cnt);
}

__global__ void gcn2_aggr_kernel(const float* __restrict__ G, const float* __restrict__ dinv,
                                 const float* __restrict__ bias, const int* __restrict__ perm1,
                                 const int* __restrict__ newid1, const int* __restrict__ rowoff,
                                 const int* __restrict__ csrsrc, float* __restrict__ out) {
    int d1 = blockIdx.x;
    int c = threadIdx.x;
    int D = perm1[d1];
    float dd = dinv[d1];
    float acc = dd * dd * G[(size_t)d1 * 128 + c];
    int r1 = rowoff[D + 1];
    for (int j = rowoff[D]; j < r1; ++j) {
        int s1 = newid1[csrsrc[j]];
        if (s1 >= 0) acc += dinv[s1] * dd * G[(size_t)s1 * 128 + c];
    }
    out[(size_t)d1 * 128 + c] = fmaxf(acc + bias[c], 0.f);
}

// ---------------- SAG scores ----------------
__global__ void score1_kernel(const float* __restrict__ X, const float* __restrict__ wrel,
                              const float* __restrict__ brel, const float* __restrict__ wroot,
                              const int* __restrict__ rowoff, const int* __restrict__ csrsrc,
                              float* __restrict__ score) {
    int d = blockIdx.x;
    int c = threadIdx.x;  // 128
    float aggc = 0.f;
    int r1 = rowoff[d + 1];
    for (int j = rowoff[d]; j < r1; ++j) aggc += X[(size_t)csrsrc[j] * 128 + c];
    float part = aggc * wrel[c] + X[(size_t)d * 128 + c] * wroot[c];
    __shared__ float sw[4];
#pragma unroll
    for (int o = 16; o; o >>= 1) part += __shfl_xor_sync(0xffffffffu, part, o);
    if ((c & 31) == 0) sw[c >> 5] = part;
    __syncthreads();
    if (c == 0) score[d] = sw[0] + sw[1] + sw[2] + sw[3] + brel[0];
}

__global__ void score2_kernel(const float* __restrict__ X, const float* __restrict__ wrel,
                              const float* __restrict__ brel, const float* __restrict__ wroot,
                              const int* __restrict__ rowoff, const int* __restrict__ csrsrc,
                              const int* __restrict__ perm1, const int* __restrict__ newid1,
                              float* __restrict__ score) {
    int d1 = blockIdx.x;
    int c = threadIdx.x;
    int D = perm1[d1];
    float aggc = 0.f;
    int r1 = rowoff[D + 1];
    for (int j = rowoff[D]; j < r1; ++j) {
        int s1 = newid1[csrsrc[j]];
        if (s1 >= 0) aggc += X[(size_t)s1 * 128 + c];
    }
    float part = aggc * wrel[c] + X[(size_t)d1 * 128 + c] * wroot[c];
    __shared__ float sw[4];
#pragma unroll
    for (int o = 16; o; o >>= 1) part += __shfl_xor_sync(0xffffffffu, part, o);
    if ((c & 31) == 0) sw[c >> 5] = part;
    __syncthreads();
    if (c == 0) score[d1] = sw[0] + sw[1] + sw[2] + sw[3] + brel[0];
}

// ---------------- per-graph top-k via bitonic sort ----------------
template <int NS>
__global__ void __launch_bounds__(1024) topk_kernel(const float* __restrict__ score, int k,
                                                    int* __restrict__ perm, int* __restrict__ newid) {
    __shared__ unsigned long long keys[NS];
    int g = blockIdx.x;
    int tid = threadIdx.x;
    for (int i = tid; i < NS; i += 1024) {
        float v = score[g * NS + i];
        unsigned u = __float_as_uint(v);
        u = (u & 0x80000000u) ? ~u : (u | 0x80000000u);  // monotone increasing
        u = ~u;                                          // monotone decreasing
        keys[i] = ((unsigned long long)u << 32) | (unsigned)i;
        newid[g * NS + i] = -1;
    }
    __syncthreads();
    for (int ksz = 2; ksz <= NS; ksz <<= 1) {
        for (int j = ksz >> 1; j > 0; j >>= 1) {
            for (int i = tid; i < NS; i += 1024) {
                int ixj = i ^ j;
                if (ixj > i) {
                    bool up = ((i & ksz) == 0);
                    unsigned long long a = keys[i], b = keys[ixj];
                    if ((a > b) == up) { keys[i] = b; keys[ixj] = a; }
                }
            }
            __syncthreads();
        }
    }
    for (int r = tid; r < k; r += 1024) {
        int i = (int)(keys[r] & 0xFFFFFFFFu);
        int orig = g * NS + i;
        perm[g * k + r] = orig;
        newid[orig] = g * k + r;
    }
}

__global__ void gather_tanh_kernel(const float* __restrict__ X, const float* __restrict__ score,
                                   const int* __restrict__ perm, float* __restrict__ Xp, int np) {
    int idx = blockIdx.x * blockDim.x + threadIdx.x;
    if (idx >= np * 128) return;
    int p = idx >> 7, c = idx & 127;
    int o = perm[p];
    Xp[idx] = X[(size_t)o * 128 + c] * tanhf(score[o]);
}

// ---------------- pooling + MLP ----------------
__global__ void meanpool_kernel(const float* __restrict__ Xp2, float* __restrict__ g) {
    int gr = blockIdx.x;
    int c = threadIdx.x;  // 128
    float s = 0.f;
    for (int j = 0; j < K2; ++j) s += Xp2[(size_t)(gr * K2 + j) * 128 + c];
    g[gr * 128 + c] = s * (1.f / (float)K2);
}

__global__ void mlp_kernel(const float* __restrict__ g,
                           const float* __restrict__ fc1_w, const float* __restrict__ fc1_b,
                           const float* __restrict__ fc2_w, const float* __restrict__ fc2_b,
                           const float* __restrict__ out_w, const float* __restrict__ out_b,
                           float* __restrict__ out) {
    int gr = blockIdx.x;
    int t = threadIdx.x;  // 256
    __shared__ float xin[128], a1[256], a2[128];
    if (t < 128) xin[t] = g[gr * 128 + t];
    __syncthreads();
    {
        float s = fc1_b[t];
#pragma unroll 4
        for (int c = 0; c < 128; ++c) s += fc1_w[t * 128 + c] * xin[c];
        a1[t] = fmaxf(s, 0.f);
    }
    __syncthreads();
    if (t < 128) {
        float s = fc2_b[t];
#pragma unroll 4
        for (int c = 0; c < 256; ++c) s += fc2_w[t * 256 + c] * a1[c];
        a2[t] = fmaxf(s, 0.f);
    }
    __syncthreads();
    if (t < 10) {
        float s = out_b[t];
#pragma unroll 4
        for (int c = 0; c < 128; ++c) s += out_w[t * 128 + c] * a2[c];
        out[gr * 10 + t] = s;
    }
}

// ---------------- launch ----------------
extern "C" void kernel_launch(void* const* d_in, const int* in_sizes, int n_in,
                              void* d_out, int out_size) {
    const float* x         = (const float*)d_in[0];
    const int*   src       = (const int*)d_in[1];
    const int*   dst       = src + NEDGES;
    const float* gat1_w    = (const float*)d_in[3];
    const float* gat1_asrc = (const float*)d_in[4];
    const float* gat1_adst = (const float*)d_in[5];
    const float* gat1_b    = (const float*)d_in[6];
    const float* gat2_w    = (const float*)d_in[7];
    const float* gat2_asrc = (const float*)d_in[8];
    const float* gat2_adst = (const float*)d_in[9];
    const float* gat2_b    = (const float*)d_in[10];
    const float* gcn1_w    = (const float*)d_in[11];
    const float* gcn1_b    = (const float*)d_in[12];
    const float* sag1_wrel = (const float*)d_in[13];
    const float* sag1_brel = (const float*)d_in[14];
    const float* sag1_wroot= (const float*)d_in[15];
    const float* gcn2_w    = (const float*)d_in[16];
    const float* gcn2_b    = (const float*)d_in[17];
    const float* sag2_wrel = (const float*)d_in[18];
    const float* sag2_brel = (const float*)d_in[19];
    const float* sag2_wroot= (const float*)d_in[20];
    const float* fc1_w     = (const float*)d_in[21];
    const float* fc1_b     = (const float*)d_in[22];
    const float* fc2_w     = (const float*)d_in[23];
    const float* fc2_b     = (const float*)d_in[24];
    const float* out_w     = (const float*)d_in[25];
    const float* out_b     = (const float*)d_in[26];
    float* outp = (float*)d_out;

    float *pA, *pB, *pAS, *pAD, *pF1, *pF2, *pX1P, *pH3, *pX2, *pX2P, *pScore, *pDinv, *pPool;
    int *pCnt, *pFill, *pRow, *pCsr, *pPerm1, *pNew1, *pPerm2, *pNew2;
    cudaGetSymbolAddress((void**)&pA, g_bufA);
    cudaGetSymbolAddress((void**)&pB, g_bufB);
    cudaGetSymbolAddress((void**)&pAS, g_as);
    cudaGetSymbolAddress((void**)&pAD, g_ad);
    cudaGetSymbolAddress((void**)&pF1, g_feat1);
    cudaGetSymbolAddress((void**)&pF2, g_feat2);
    cudaGetSymbolAddress((void**)&pX1P, g_x1p);
    cudaGetSymbolAddress((void**)&pH3, g_h3);
    cudaGetSymbolAddress((void**)&pX2, g_x2);
    cudaGetSymbolAddress((void**)&pX2P, g_x2p);
    cudaGetSymbolAddress((void**)&pScore, g_score);
    cudaGetSymbolAddress((void**)&pDinv, g_dinv);
    cudaGetSymbolAddress((void**)&pPool, g_pool);
    cudaGetSymbolAddress((void**)&pCnt, g_cnt);
    cudaGetSymbolAddress((void**)&pFill, g_fill);
    cudaGetSymbolAddress((void**)&pRow, g_rowoff);
    cudaGetSymbolAddress((void**)&pCsr, g_csrsrc);
    cudaGetSymbolAddress((void**)&pPerm1, g_perm1);
    cudaGetSymbolAddress((void**)&pNew1, g_newid1);
    cudaGetSymbolAddress((void**)&pPerm2, g_perm2);
    cudaGetSymbolAddress((void**)&pNew2, g_newid2);

    // ---- CSR by dst ----
    zero2_kernel<<<(NNODES + 255) / 256, 256>>>(pCnt, pFill, NNODES);
    count_dst_kernel<<<(NEDGES + 255) / 256, 256>>>(dst, pCnt);
    scan_kernel<<<1, 1024>>>(pCnt, pRow);
    fill_csr_kernel<<<(NEDGES + 255) / 256, 256>>>(src, dst, pRow, pFill, pCsr);

    // ---- GAT1 (64 -> 4x64, relu) ----
    gemm_nt<<<dim3(2, NNODES / 128), 256>>>(x, gat1_w, pA, NNODES, 256, 64);
    attn_sums_kernel<<<(NNODES * 4 + 255) / 256, 256>>>(pA, gat1_asrc, gat1_adst, pAS, pAD);
    gat_aggr_kernel<<<NNODES, 256>>>(pA, pAS, pAD, gat1_b, pRow, pCsr, pB, 1);

    // ---- GAT2 (256 -> 4x64) ----
    gemm_nt<<<dim3(2, NNODES / 128), 256>>>(pB, gat2_w, pA, NNODES, 256, 256);
    attn_sums_kernel<<<(NNODES * 4 + 255) / 256, 256>>>(pA, gat2_asrc, gat2_adst, pAS, pAD);
    gat_aggr_kernel<<<NNODES, 256>>>(pA, pAS, pAD, gat2_b, pRow, pCsr, pB, 0);

    // ---- GCN1 (256 -> 128, relu) ----
    gemm_nt<<<dim3(1, NNODES / 128), 256>>>(pB, gcn1_w, pF1, NNODES, 128, 256);
    dinv1_kernel<<<(NNODES + 255) / 256, 256>>>(pRow, pDinv);
    gcn1_aggr_kernel<<<NNODES, 128>>>(pF1, pDinv, gcn1_b, pRow, pCsr, pF2);

    // ---- SAGPool1 (ratio .5) ----
    score1_kernel<<<NNODES, 128>>>(pF2, sag1_wrel, sag1_brel, sag1_wroot, pRow, pCsr, pScore);
    topk_kernel<NPG><<<NGRAPH, 1024>>>(pScore, K1, pPerm1, pNew1);
    gather_tanh_kernel<<<(NP1 * 128 + 255) / 256, 256>>>(pF2, pScore, pPerm1, pX1P, NP1);

    // ---- GCN2 (128 -> 128, relu) on pooled graph via original CSR + remap ----
    gemm_nt<<<dim3(1, NP1 / 128), 256>>>(pX1P, gcn2_w, pH3, NP1, 128, 128);
    gcn2_deg_kernel<<<(NP1 + 255) / 256, 256>>>(pPerm1, pNew1, pRow, pCsr, pDinv);
    gcn2_aggr_kernel<<<NP1, 128>>>(pH3, pDinv, gcn2_b, pPerm1, pNew1, pRow, pCsr, pX2);

    // ---- SAGPool2 ----
    score2_kernel<<<NP1, 128>>>(pX2, sag2_wrel, sag2_brel, sag2_wroot, pRow, pCsr, pPerm1, pNew1, pScore);
    topk_kernel<K1><<<NGRAPH, 1024>>>(pScore, K2, pPerm2, pNew2);
    gather_tanh_kernel<<<(NP2 * 128 + 255) / 256, 256>>>(pX2, pScore, pPerm2, pX2P, NP2);

    // ---- global mean pool + classifier ----
    meanpool_kernel<<<NGRAPH, 128>>>(pX2P, pPool);
    mlp_kernel<<<NGRAPH, 256>>>(pPool, fc1_w, fc1_b, fc2_w, fc2_b, out_w, out_b, outp);
}